// round 3
// baseline (speedup 1.0000x reference)
#include <cuda_runtime.h>
#include <cuda_bf16.h>
#include <cstdint>

// ---------------------------------------------------------------------------
// GCN layer: out = segment_sum(x[edge_col] * edge_val, edge_row) @ W + bias
//   N nodes = out_size / 128, E edges = in_sizes[1], D_IN = D_OUT = 128.
//   edge_row is SORTED -> one warp per node, binary-search its edge range,
//   accumulate row in registers, no atomics. Then fp32 SGEMM + bias.
// ---------------------------------------------------------------------------

#define D 128
#define MAX_NODES 100000

// Scratch for the intermediate support matrix (static device array: no allocs).
// Referenced directly as a symbol from inside the kernels — no host-side
// cudaGetSymbolAddress during graph capture.
__device__ float g_support[(size_t)MAX_NODES * D];

__device__ __forceinline__ int lower_bound_i32(const int* __restrict__ a, int n, int key) {
    int lo = 0, hi = n;
    while (lo < hi) {
        int mid = (lo + hi) >> 1;
        if (a[mid] < key) lo = mid + 1; else hi = mid;
    }
    return lo;
}

// ---------------------------------------------------------------------------
// Kernel 1: SpMM (A @ X). One warp per node; lane l owns dims [4l, 4l+4).
// ---------------------------------------------------------------------------
__global__ void __launch_bounds__(256) spmm_kernel(
    const float* __restrict__ x,        // [N, 128]
    const int*   __restrict__ erow,     // [E] sorted
    const int*   __restrict__ ecol,     // [E]
    const float* __restrict__ eval,     // [E]
    int N, int E)
{
    const int warp_in_blk = threadIdx.x >> 5;
    const int lane        = threadIdx.x & 31;
    const int node        = blockIdx.x * 8 + warp_in_blk;
    if (node >= N) return;

    // All lanes run the same (uniform) binary searches; cheap & cached.
    const int lo = lower_bound_i32(erow, E, node);
    const int hi = lower_bound_i32(erow, E, node + 1);

    float4 acc = make_float4(0.f, 0.f, 0.f, 0.f);

    for (int base = lo; base < hi; base += 32) {
        const int idx = base + lane;
        int   cc = 0;
        float vv = 0.f;
        if (idx < hi) { cc = ecol[idx]; vv = eval[idx]; }
        const int cnt = min(32, hi - base);

        if (cnt == 32) {
            #pragma unroll
            for (int j = 0; j < 32; j++) {
                const int   cj = __shfl_sync(0xffffffffu, cc, j);
                const float vj = __shfl_sync(0xffffffffu, vv, j);
                const float4 xv = *((const float4*)(x + (size_t)cj * D) + lane);
                acc.x += vj * xv.x;
                acc.y += vj * xv.y;
                acc.z += vj * xv.z;
                acc.w += vj * xv.w;
            }
        } else {
            for (int j = 0; j < cnt; j++) {
                const int   cj = __shfl_sync(0xffffffffu, cc, j);
                const float vj = __shfl_sync(0xffffffffu, vv, j);
                const float4 xv = *((const float4*)(x + (size_t)cj * D) + lane);
                acc.x += vj * xv.x;
                acc.y += vj * xv.y;
                acc.z += vj * xv.z;
                acc.w += vj * xv.w;
            }
        }
    }

    *((float4*)(g_support + (size_t)node * D) + lane) = acc;
}

// ---------------------------------------------------------------------------
// Kernel 2: SGEMM  out[M,128] = g_support[M,128] @ W[128,128] + bias
// 128x128 block tile, 256 threads, 8x8 microtile, KC=8.
// ---------------------------------------------------------------------------
__global__ void __launch_bounds__(256) gemm_kernel(
    const float* __restrict__ Wm,    // [128, 128]
    const float* __restrict__ bias,  // [128]
    float*       __restrict__ out,   // [M, 128]
    int M)
{
    __shared__ float As[8][D];   // As[k][r]  (A transposed into smem)
    __shared__ float Bs[8][D];   // Bs[k][c]

    const int tid  = threadIdx.x;          // 0..255
    const int tx   = tid & 15;             // col group (0..15) -> cols tx*8..tx*8+7
    const int ty   = tid >> 4;             // row group (0..15) -> rows ty*8..ty*8+7
    const int row0 = blockIdx.x * 128;

    // A-load mapping: thread -> (row lr, k-seg lseg)
    const int lr   = tid >> 1;             // 0..127
    const int lseg = (tid & 1) * 4;        // 0 or 4
    // B-load mapping
    const int bk = tid >> 5;               // 0..7
    const int bc = (tid & 31) * 4;         // 0..124

    float acc[8][8];
    #pragma unroll
    for (int i = 0; i < 8; i++)
        #pragma unroll
        for (int j = 0; j < 8; j++) acc[i][j] = 0.f;

    const float* S = g_support;

    for (int kk = 0; kk < D; kk += 8) {
        // Load A tile (transposed) — guard rows past M
        float4 av = make_float4(0.f, 0.f, 0.f, 0.f);
        const int gr = row0 + lr;
        if (gr < M) av = *(const float4*)(S + (size_t)gr * D + kk + lseg);
        As[lseg + 0][lr] = av.x;
        As[lseg + 1][lr] = av.y;
        As[lseg + 2][lr] = av.z;
        As[lseg + 3][lr] = av.w;

        // Load B tile
        *(float4*)&Bs[bk][bc] = *(const float4*)(Wm + (size_t)(kk + bk) * D + bc);

        __syncthreads();

        #pragma unroll
        for (int k = 0; k < 8; k++) {
            float a[8], b[8];
            *(float4*)&a[0] = *(const float4*)&As[k][ty * 8];
            *(float4*)&a[4] = *(const float4*)&As[k][ty * 8 + 4];
            *(float4*)&b[0] = *(const float4*)&Bs[k][tx * 8];
            *(float4*)&b[4] = *(const float4*)&Bs[k][tx * 8 + 4];
            #pragma unroll
            for (int i = 0; i < 8; i++)
                #pragma unroll
                for (int j = 0; j < 8; j++)
                    acc[i][j] += a[i] * b[j];
        }
        __syncthreads();
    }

    // Epilogue: add bias, store
    float bz[8];
    #pragma unroll
    for (int j = 0; j < 8; j++) bz[j] = bias[tx * 8 + j];

    #pragma unroll
    for (int i = 0; i < 8; i++) {
        const int gr = row0 + ty * 8 + i;
        if (gr < M) {
            float4 v0, v1;
            v0.x = acc[i][0] + bz[0];
            v0.y = acc[i][1] + bz[1];
            v0.z = acc[i][2] + bz[2];
            v0.w = acc[i][3] + bz[3];
            v1.x = acc[i][4] + bz[4];
            v1.y = acc[i][5] + bz[5];
            v1.z = acc[i][6] + bz[6];
            v1.w = acc[i][7] + bz[7];
            *(float4*)(out + (size_t)gr * D + tx * 8)     = v0;
            *(float4*)(out + (size_t)gr * D + tx * 8 + 4) = v1;
        }
    }
}

// ---------------------------------------------------------------------------
// Launch
// ---------------------------------------------------------------------------
extern "C" void kernel_launch(void* const* d_in, const int* in_sizes, int n_in,
                              void* d_out, int out_size)
{
    const float* x    = (const float*)d_in[0];   // [N,128]
    const int*   erow = (const int*)  d_in[1];   // [E] sorted
    const int*   ecol = (const int*)  d_in[2];   // [E]
    const float* eval = (const float*)d_in[3];   // [E]
    const float* Wm   = (const float*)d_in[4];   // [128,128]
    const float* bias = (const float*)d_in[5];   // [128]
    float*       out  = (float*)d_out;

    const int N = out_size / D;
    const int E = in_sizes[1];

    // Kernel 1: SpMM — 8 warps/block, one warp per node.
    {
        dim3 blk(256);
        dim3 grd((N + 7) / 8);
        spmm_kernel<<<grd, blk>>>(x, erow, ecol, eval, N, E);
    }

    // Kernel 2: GEMM + bias
    {
        dim3 blk(256);
        dim3 grd((N + 127) / 128);
        gemm_kernel<<<grd, blk>>>(Wm, bias, out, N);
    }
}

// round 7
// speedup vs baseline: 1.2357x; 1.2357x over previous
#include <cuda_runtime.h>
#include <cuda_bf16.h>
#include <cstdint>

// ---------------------------------------------------------------------------
// GCN layer, reordered:  out = A @ (x @ W) + bias
//   Kernel 1: xw = x @ W          (tf32 tensor-core GEMM, N x 128 @ 128 x 128)
//   Kernel 2: out = A @ xw + bias (sorted-row SpMM, one warp per node, no atomics)
// ---------------------------------------------------------------------------

#define D 128
#define MAX_NODES 100000

// Scratch for xw (static device array: no allocs).
__device__ float g_xw[(size_t)MAX_NODES * D];

__device__ __forceinline__ uint32_t f2tf32(float f) {
    uint32_t r;
    asm("cvt.rna.tf32.f32 %0, %1;" : "=r"(r) : "f"(f));
    return r;
}

__device__ __forceinline__ void mma16n8k8(float* c, const uint32_t* a,
                                          uint32_t b0, uint32_t b1) {
    asm volatile(
        "mma.sync.aligned.m16n8k8.row.col.f32.tf32.tf32.f32 "
        "{%0,%1,%2,%3}, {%4,%5,%6,%7}, {%8,%9}, {%0,%1,%2,%3};"
        : "+f"(c[0]), "+f"(c[1]), "+f"(c[2]), "+f"(c[3])
        : "r"(a[0]), "r"(a[1]), "r"(a[2]), "r"(a[3]), "r"(b0), "r"(b1));
}

__device__ __forceinline__ int lower_bound_i32(const int* __restrict__ a, int n, int key) {
    int lo = 0, hi = n;
    while (lo < hi) {
        int mid = (lo + hi) >> 1;
        if (a[mid] < key) lo = mid + 1; else hi = mid;
    }
    return lo;
}

// ---------------------------------------------------------------------------
// Kernel 1: xw = x @ W   (tf32 mma, 128x128 block tile, 8 warps)
// Warp tile 32x64: 2 m-frags x 8 n-frags of m16n8k8.
// ---------------------------------------------------------------------------
__global__ void __launch_bounds__(256) xw_kernel(
    const float* __restrict__ x,    // [M, 128]
    const float* __restrict__ Wm,   // [128, 128] (k-major rows)
    int M)
{
    __shared__ uint32_t As[128][36];   // x chunk [128 rows][32 k] (+4 pad)
    __shared__ uint32_t Ws[32][136];   // W chunk [32 k][128 n]    (+8 pad)

    const int tid  = threadIdx.x;
    const int lane = tid & 31;
    const int wid  = tid >> 5;
    const int wm   = wid & 3;          // warp row group (0..3)  -> rows wm*32..+31
    const int wn   = wid >> 2;         // warp col group (0..1)  -> cols wn*64..+63
    const int row0 = blockIdx.x * 128;

    const int gID = lane >> 2;         // 0..7
    const int tig = lane & 3;          // 0..3

    float c[2][8][4];
    #pragma unroll
    for (int m = 0; m < 2; m++)
        #pragma unroll
        for (int n = 0; n < 8; n++)
            #pragma unroll
            for (int i = 0; i < 4; i++) c[m][n][i] = 0.f;

    for (int kc = 0; kc < D; kc += 32) {
        // Load x chunk: 128 rows x 32 cols (1024 float4, 4 per thread)
        #pragma unroll
        for (int it = 0; it < 4; it++) {
            int s   = tid + it * 256;
            int row = s >> 3;
            int seg = (s & 7) * 4;
            float4 v = make_float4(0.f, 0.f, 0.f, 0.f);
            if (row0 + row < M)
                v = *(const float4*)(x + (size_t)(row0 + row) * D + kc + seg);
            As[row][seg + 0] = f2tf32(v.x);
            As[row][seg + 1] = f2tf32(v.y);
            As[row][seg + 2] = f2tf32(v.z);
            As[row][seg + 3] = f2tf32(v.w);
        }
        // Load W chunk: 32 k-rows x 128 cols (1024 float4, 4 per thread)
        #pragma unroll
        for (int it = 0; it < 4; it++) {
            int s   = tid + it * 256;
            int row = s >> 5;
            int seg = (s & 31) * 4;
            float4 v = *(const float4*)(Wm + (size_t)(kc + row) * D + seg);
            Ws[row][seg + 0] = f2tf32(v.x);
            Ws[row][seg + 1] = f2tf32(v.y);
            Ws[row][seg + 2] = f2tf32(v.z);
            Ws[row][seg + 3] = f2tf32(v.w);
        }
        __syncthreads();

        #pragma unroll
        for (int km = 0; km < 4; km++) {
            const int k8 = km * 8;
            uint32_t a[2][4];
            #pragma unroll
            for (int m = 0; m < 2; m++) {
                const int rb = wm * 32 + m * 16;
                a[m][0] = As[rb + gID    ][k8 + tig    ];
                a[m][1] = As[rb + gID + 8][k8 + tig    ];
                a[m][2] = As[rb + gID    ][k8 + tig + 4];
                a[m][3] = As[rb + gID + 8][k8 + tig + 4];
            }
            #pragma unroll
            for (int n = 0; n < 8; n++) {
                const int cb = wn * 64 + n * 8;
                const uint32_t b0 = Ws[k8 + tig    ][cb + gID];
                const uint32_t b1 = Ws[k8 + tig + 4][cb + gID];
                mma16n8k8(c[0][n], a[0], b0, b1);
                mma16n8k8(c[1][n], a[1], b0, b1);
            }
        }
        __syncthreads();
    }

    // Epilogue: write xw fragments
    #pragma unroll
    for (int m = 0; m < 2; m++) {
        const int r0 = row0 + wm * 32 + m * 16 + gID;
        const int r1 = r0 + 8;
        #pragma unroll
        for (int n = 0; n < 8; n++) {
            const int cb = wn * 64 + n * 8 + 2 * tig;
            if (r0 < M) {
                float2 v = make_float2(c[m][n][0], c[m][n][1]);
                *(float2*)(g_xw + (size_t)r0 * D + cb) = v;
            }
            if (r1 < M) {
                float2 v = make_float2(c[m][n][2], c[m][n][3]);
                *(float2*)(g_xw + (size_t)r1 * D + cb) = v;
            }
        }
    }
}

// ---------------------------------------------------------------------------
// Kernel 2: out = A @ xw + bias. One warp per node; lane l owns dims [4l,4l+4).
// Dual accumulators break the serial FFMA chain.
// ---------------------------------------------------------------------------
__global__ void __launch_bounds__(256) spmm_kernel(
    const int*   __restrict__ erow,   // [E] sorted
    const int*   __restrict__ ecol,   // [E]
    const float* __restrict__ eval,   // [E]
    const float* __restrict__ bias,   // [128]
    float*       __restrict__ out,    // [N, 128]
    int N, int E)
{
    const int warp_in_blk = threadIdx.x >> 5;
    const int lane        = threadIdx.x & 31;
    const int node        = blockIdx.x * 8 + warp_in_blk;
    if (node >= N) return;

    const int lo = lower_bound_i32(erow, E, node);
    const int hi = lower_bound_i32(erow, E, node + 1);

    float4 acc0 = make_float4(0.f, 0.f, 0.f, 0.f);
    float4 acc1 = make_float4(0.f, 0.f, 0.f, 0.f);

    for (int base = lo; base < hi; base += 32) {
        const int idx = base + lane;
        int   cc = 0;
        float vv = 0.f;
        if (idx < hi) { cc = ecol[idx]; vv = eval[idx]; }
        const int cnt = min(32, hi - base);

        if (cnt == 32) {
            #pragma unroll
            for (int j = 0; j < 32; j += 2) {
                {
                    const int   cj = __shfl_sync(0xffffffffu, cc, j);
                    const float vj = __shfl_sync(0xffffffffu, vv, j);
                    const float4 xv = *((const float4*)(g_xw + (size_t)cj * D) + lane);
                    acc0.x += vj * xv.x;  acc0.y += vj * xv.y;
                    acc0.z += vj * xv.z;  acc0.w += vj * xv.w;
                }
                {
                    const int   cj = __shfl_sync(0xffffffffu, cc, j + 1);
                    const float vj = __shfl_sync(0xffffffffu, vv, j + 1);
                    const float4 xv = *((const float4*)(g_xw + (size_t)cj * D) + lane);
                    acc1.x += vj * xv.x;  acc1.y += vj * xv.y;
                    acc1.z += vj * xv.z;  acc1.w += vj * xv.w;
                }
            }
        } else {
            for (int j = 0; j < cnt; j++) {
                const int   cj = __shfl_sync(0xffffffffu, cc, j);
                const float vj = __shfl_sync(0xffffffffu, vv, j);
                const float4 xv = *((const float4*)(g_xw + (size_t)cj * D) + lane);
                acc0.x += vj * xv.x;  acc0.y += vj * xv.y;
                acc0.z += vj * xv.z;  acc0.w += vj * xv.w;
            }
        }
    }

    const float4 b4 = *((const float4*)bias + lane);
    float4 r;
    r.x = acc0.x + acc1.x + b4.x;
    r.y = acc0.y + acc1.y + b4.y;
    r.z = acc0.z + acc1.z + b4.z;
    r.w = acc0.w + acc1.w + b4.w;
    *((float4*)(out + (size_t)node * D) + lane) = r;
}

// ---------------------------------------------------------------------------
// Launch
// ---------------------------------------------------------------------------
extern "C" void kernel_launch(void* const* d_in, const int* in_sizes, int n_in,
                              void* d_out, int out_size)
{
    const float* x    = (const float*)d_in[0];   // [N,128]
    const int*   erow = (const int*)  d_in[1];   // [E] sorted
    const int*   ecol = (const int*)  d_in[2];   // [E]
    const float* eval = (const float*)d_in[3];   // [E]
    const float* Wm   = (const float*)d_in[4];   // [128,128]
    const float* bias = (const float*)d_in[5];   // [128]
    float*       out  = (float*)d_out;

    const int N = out_size / D;
    const int E = in_sizes[1];

    // Kernel 1: xw = x @ W (tf32 tensor cores)
    {
        dim3 blk(256);
        dim3 grd((N + 127) / 128);
        xw_kernel<<<grd, blk>>>(x, Wm, N);
    }

    // Kernel 2: out = A @ xw + bias
    {
        dim3 blk(256);
        dim3 grd((N + 7) / 8);
        spmm_kernel<<<grd, blk>>>(erow, ecol, eval, bias, out, N, E);
    }
}

// round 8
// speedup vs baseline: 1.7976x; 1.4548x over previous
#include <cuda_runtime.h>
#include <cuda_bf16.h>
#include <cstdint>

// ---------------------------------------------------------------------------
// GCN layer, reordered:  out = A @ (x @ W) + bias
//   Kernel 0: row_ptr from sorted COO rows (kills per-warp binary search)
//   Kernel 1: xw = x @ W          (tf32 tensor-core GEMM)
//   Kernel 2: out = A @ xw + bias (CSR SpMM, one warp per node, no atomics,
//                                  8-deep explicit gather pipeline)
// ---------------------------------------------------------------------------

#define D 128
#define MAX_NODES 100000

__device__ float g_xw[(size_t)MAX_NODES * D];
__device__ int   g_row_ptr[MAX_NODES + 1];

__device__ __forceinline__ uint32_t f2tf32(float f) {
    uint32_t r;
    asm("cvt.rna.tf32.f32 %0, %1;" : "=r"(r) : "f"(f));
    return r;
}

__device__ __forceinline__ void mma16n8k8(float* c, const uint32_t* a,
                                          uint32_t b0, uint32_t b1) {
    asm volatile(
        "mma.sync.aligned.m16n8k8.row.col.f32.tf32.tf32.f32 "
        "{%0,%1,%2,%3}, {%4,%5,%6,%7}, {%8,%9}, {%0,%1,%2,%3};"
        : "+f"(c[0]), "+f"(c[1]), "+f"(c[2]), "+f"(c[3])
        : "r"(a[0]), "r"(a[1]), "r"(a[2]), "r"(a[3]), "r"(b0), "r"(b1));
}

// ---------------------------------------------------------------------------
// Kernel 0: CSR row_ptr from sorted COO rows. One thread per edge.
// row_ptr[r] = first edge index with erow >= r;  row_ptr[N] = E.
// ---------------------------------------------------------------------------
__global__ void __launch_bounds__(256) build_row_ptr_kernel(
    const int* __restrict__ erow, int N, int E)
{
    const int i = blockIdx.x * blockDim.x + threadIdx.x;
    if (i >= E) return;
    const int r1 = erow[i];
    const int r0 = (i == 0) ? -1 : erow[i - 1];
    for (int r = r0 + 1; r <= r1; r++) g_row_ptr[r] = i;
    if (i == E - 1) {
        for (int r = r1 + 1; r <= N; r++) g_row_ptr[r] = E;
    }
}

// ---------------------------------------------------------------------------
// Kernel 1: xw = x @ W   (tf32 mma, 128x128 block tile, 8 warps)
// ---------------------------------------------------------------------------
__global__ void __launch_bounds__(256) xw_kernel(
    const float* __restrict__ x,    // [M, 128]
    const float* __restrict__ Wm,   // [128, 128]
    int M)
{
    __shared__ uint32_t As[128][36];
    __shared__ uint32_t Ws[32][136];

    const int tid  = threadIdx.x;
    const int lane = tid & 31;
    const int wid  = tid >> 5;
    const int wm   = wid & 3;
    const int wn   = wid >> 2;
    const int row0 = blockIdx.x * 128;

    const int gID = lane >> 2;
    const int tig = lane & 3;

    float c[2][8][4];
    #pragma unroll
    for (int m = 0; m < 2; m++)
        #pragma unroll
        for (int n = 0; n < 8; n++)
            #pragma unroll
            for (int i = 0; i < 4; i++) c[m][n][i] = 0.f;

    for (int kc = 0; kc < D; kc += 32) {
        #pragma unroll
        for (int it = 0; it < 4; it++) {
            int s   = tid + it * 256;
            int row = s >> 3;
            int seg = (s & 7) * 4;
            float4 v = make_float4(0.f, 0.f, 0.f, 0.f);
            if (row0 + row < M)
                v = *(const float4*)(x + (size_t)(row0 + row) * D + kc + seg);
            As[row][seg + 0] = f2tf32(v.x);
            As[row][seg + 1] = f2tf32(v.y);
            As[row][seg + 2] = f2tf32(v.z);
            As[row][seg + 3] = f2tf32(v.w);
        }
        #pragma unroll
        for (int it = 0; it < 4; it++) {
            int s   = tid + it * 256;
            int row = s >> 5;
            int seg = (s & 31) * 4;
            float4 v = *(const float4*)(Wm + (size_t)(kc + row) * D + seg);
            Ws[row][seg + 0] = f2tf32(v.x);
            Ws[row][seg + 1] = f2tf32(v.y);
            Ws[row][seg + 2] = f2tf32(v.z);
            Ws[row][seg + 3] = f2tf32(v.w);
        }
        __syncthreads();

        #pragma unroll
        for (int km = 0; km < 4; km++) {
            const int k8 = km * 8;
            uint32_t a[2][4];
            #pragma unroll
            for (int m = 0; m < 2; m++) {
                const int rb = wm * 32 + m * 16;
                a[m][0] = As[rb + gID    ][k8 + tig    ];
                a[m][1] = As[rb + gID + 8][k8 + tig    ];
                a[m][2] = As[rb + gID    ][k8 + tig + 4];
                a[m][3] = As[rb + gID + 8][k8 + tig + 4];
            }
            #pragma unroll
            for (int n = 0; n < 8; n++) {
                const int cb = wn * 64 + n * 8;
                const uint32_t b0 = Ws[k8 + tig    ][cb + gID];
                const uint32_t b1 = Ws[k8 + tig + 4][cb + gID];
                mma16n8k8(c[0][n], a[0], b0, b1);
                mma16n8k8(c[1][n], a[1], b0, b1);
            }
        }
        __syncthreads();
    }

    #pragma unroll
    for (int m = 0; m < 2; m++) {
        const int r0 = row0 + wm * 32 + m * 16 + gID;
        const int r1 = r0 + 8;
        #pragma unroll
        for (int n = 0; n < 8; n++) {
            const int cb = wn * 64 + n * 8 + 2 * tig;
            if (r0 < M) {
                float2 v = make_float2(c[m][n][0], c[m][n][1]);
                *(float2*)(g_xw + (size_t)r0 * D + cb) = v;
            }
            if (r1 < M) {
                float2 v = make_float2(c[m][n][2], c[m][n][3]);
                *(float2*)(g_xw + (size_t)r1 * D + cb) = v;
            }
        }
    }
}

// ---------------------------------------------------------------------------
// Kernel 2: out = A @ xw + bias. One warp per node; lane l owns dims [4l,4l+4).
// row_ptr lookup (no search); 8-deep explicit gather batches for MLP.
// ---------------------------------------------------------------------------
__global__ void __launch_bounds__(256) spmm_kernel(
    const int*   __restrict__ ecol,   // [E]
    const float* __restrict__ eval,   // [E]
    const float* __restrict__ bias,   // [128]
    float*       __restrict__ out,    // [N, 128]
    int N)
{
    const int warp_in_blk = threadIdx.x >> 5;
    const int lane        = threadIdx.x & 31;
    const int node        = blockIdx.x * 8 + warp_in_blk;
    if (node >= N) return;

    const int lo = g_row_ptr[node];
    const int hi = g_row_ptr[node + 1];

    float4 acc0 = make_float4(0.f, 0.f, 0.f, 0.f);
    float4 acc1 = make_float4(0.f, 0.f, 0.f, 0.f);

    for (int base = lo; base < hi; base += 32) {
        const int idx = base + lane;
        int   cc = 0;
        float vv = 0.f;
        if (idx < hi) { cc = ecol[idx]; vv = eval[idx]; }
        const int cnt = min(32, hi - base);

        if (cnt == 32) {
            #pragma unroll
            for (int jb = 0; jb < 32; jb += 8) {
                float4 xv[8];
                float  vj[8];
                #pragma unroll
                for (int u = 0; u < 8; u++) {
                    const int cj = __shfl_sync(0xffffffffu, cc, jb + u);
                    vj[u] = __shfl_sync(0xffffffffu, vv, jb + u);
                    xv[u] = *((const float4*)(g_xw + (size_t)cj * D) + lane);
                }
                #pragma unroll
                for (int u = 0; u < 8; u += 2) {
                    acc0.x += vj[u] * xv[u].x;      acc0.y += vj[u] * xv[u].y;
                    acc0.z += vj[u] * xv[u].z;      acc0.w += vj[u] * xv[u].w;
                    acc1.x += vj[u+1] * xv[u+1].x;  acc1.y += vj[u+1] * xv[u+1].y;
                    acc1.z += vj[u+1] * xv[u+1].z;  acc1.w += vj[u+1] * xv[u+1].w;
                }
            }
        } else {
            for (int j = 0; j < cnt; j++) {
                const int   cj = __shfl_sync(0xffffffffu, cc, j);
                const float vj = __shfl_sync(0xffffffffu, vv, j);
                const float4 xv = *((const float4*)(g_xw + (size_t)cj * D) + lane);
                acc0.x += vj * xv.x;  acc0.y += vj * xv.y;
                acc0.z += vj * xv.z;  acc0.w += vj * xv.w;
            }
        }
    }

    const float4 b4 = *((const float4*)bias + lane);
    float4 r;
    r.x = acc0.x + acc1.x + b4.x;
    r.y = acc0.y + acc1.y + b4.y;
    r.z = acc0.z + acc1.z + b4.z;
    r.w = acc0.w + acc1.w + b4.w;
    *((float4*)(out + (size_t)node * D) + lane) = r;
}

// ---------------------------------------------------------------------------
// Launch
// ---------------------------------------------------------------------------
extern "C" void kernel_launch(void* const* d_in, const int* in_sizes, int n_in,
                              void* d_out, int out_size)
{
    const float* x    = (const float*)d_in[0];   // [N,128]
    const int*   erow = (const int*)  d_in[1];   // [E] sorted
    const int*   ecol = (const int*)  d_in[2];   // [E]
    const float* eval = (const float*)d_in[3];   // [E]
    const float* Wm   = (const float*)d_in[4];   // [128,128]
    const float* bias = (const float*)d_in[5];   // [128]
    float*       out  = (float*)d_out;

    const int N = out_size / D;
    const int E = in_sizes[1];

    // Kernel 0: CSR row_ptr
    build_row_ptr_kernel<<<(E + 255) / 256, 256>>>(erow, N, E);

    // Kernel 1: xw = x @ W (tf32 tensor cores)
    xw_kernel<<<(N + 127) / 128, 256>>>(x, Wm, N);

    // Kernel 2: out = A @ xw + bias
    spmm_kernel<<<(N + 7) / 8, 256>>>(ecol, eval, bias, out, N);
}

// round 10
// speedup vs baseline: 2.1451x; 1.1933x over previous
#include <cuda_runtime.h>
#include <cuda_fp16.h>
#include <cuda_bf16.h>
#include <cstdint>

// ---------------------------------------------------------------------------
// GCN layer, reordered:  out = A @ (x @ W) + bias
//   Kernel 0: row_ptr from sorted COO rows (8 edges/thread, int4 loads)
//   Kernel 1: xw = x @ W   (tf32 tensor-core GEMM, fp32 accum, fp16 store)
//   Kernel 2: out = A @ xw + bias (CSR SpMM, warp/node, fp16 gather,
//                                  fp32 accumulate, 8-deep gather batches)
// ---------------------------------------------------------------------------

#define D 128
#define MAX_NODES 100000

__device__ __half g_xw[(size_t)MAX_NODES * D];   // fp16: halves gather traffic
__device__ int    g_row_ptr[MAX_NODES + 1];

__device__ __forceinline__ uint32_t f2tf32(float f) {
    uint32_t r;
    asm("cvt.rna.tf32.f32 %0, %1;" : "=r"(r) : "f"(f));
    return r;
}

__device__ __forceinline__ void mma16n8k8(float* c, const uint32_t* a,
                                          uint32_t b0, uint32_t b1) {
    asm volatile(
        "mma.sync.aligned.m16n8k8.row.col.f32.tf32.tf32.f32 "
        "{%0,%1,%2,%3}, {%4,%5,%6,%7}, {%8,%9}, {%0,%1,%2,%3};"
        : "+f"(c[0]), "+f"(c[1]), "+f"(c[2]), "+f"(c[3])
        : "r"(a[0]), "r"(a[1]), "r"(a[2]), "r"(a[3]), "r"(b0), "r"(b1));
}

// ---------------------------------------------------------------------------
// Kernel 0: CSR row_ptr from sorted COO rows. 8 edges per thread (2x int4).
// row_ptr[r] = first edge index with erow >= r;  row_ptr[N] = E.
// ---------------------------------------------------------------------------
__global__ void __launch_bounds__(256) build_row_ptr_kernel(
    const int* __restrict__ erow, int N, int E)
{
    const int t    = blockIdx.x * blockDim.x + threadIdx.x;
    const int base = t * 8;
    if (base >= E) return;

    int v[9];
    v[0] = (base == 0) ? -1 : erow[base - 1];

    const int cnt = min(8, E - base);
    if (cnt == 8) {
        const int4 a = *(const int4*)(erow + base);
        const int4 b = *(const int4*)(erow + base + 4);
        v[1] = a.x; v[2] = a.y; v[3] = a.z; v[4] = a.w;
        v[5] = b.x; v[6] = b.y; v[7] = b.z; v[8] = b.w;
    } else {
        for (int k = 0; k < cnt; k++) v[k + 1] = erow[base + k];
    }

    #pragma unroll
    for (int k = 1; k <= 8; k++) {
        if (k <= cnt) {
            for (int r = v[k - 1] + 1; r <= v[k]; r++)
                g_row_ptr[r] = base + k - 1;
        }
    }
    if (base + cnt == E) {
        for (int r = v[cnt] + 1; r <= N; r++) g_row_ptr[r] = E;
    }
}

// ---------------------------------------------------------------------------
// Kernel 1: xw = x @ W   (tf32 mma, 128x128 block tile, 8 warps, fp16 out)
// ---------------------------------------------------------------------------
__global__ void __launch_bounds__(256) xw_kernel(
    const float* __restrict__ x,    // [M, 128]
    const float* __restrict__ Wm,   // [128, 128]
    int M)
{
    __shared__ uint32_t As[128][36];
    __shared__ uint32_t Ws[32][136];

    const int tid  = threadIdx.x;
    const int lane = tid & 31;
    const int wid  = tid >> 5;
    const int wm   = wid & 3;
    const int wn   = wid >> 2;
    const int row0 = blockIdx.x * 128;

    const int gID = lane >> 2;
    const int tig = lane & 3;

    float c[2][8][4];
    #pragma unroll
    for (int m = 0; m < 2; m++)
        #pragma unroll
        for (int n = 0; n < 8; n++)
            #pragma unroll
            for (int i = 0; i < 4; i++) c[m][n][i] = 0.f;

    for (int kc = 0; kc < D; kc += 32) {
        #pragma unroll
        for (int it = 0; it < 4; it++) {
            int s   = tid + it * 256;
            int row = s >> 3;
            int seg = (s & 7) * 4;
            float4 v = make_float4(0.f, 0.f, 0.f, 0.f);
            if (row0 + row < M)
                v = *(const float4*)(x + (size_t)(row0 + row) * D + kc + seg);
            As[row][seg + 0] = f2tf32(v.x);
            As[row][seg + 1] = f2tf32(v.y);
            As[row][seg + 2] = f2tf32(v.z);
            As[row][seg + 3] = f2tf32(v.w);
        }
        #pragma unroll
        for (int it = 0; it < 4; it++) {
            int s   = tid + it * 256;
            int row = s >> 5;
            int seg = (s & 31) * 4;
            float4 v = *(const float4*)(Wm + (size_t)(kc + row) * D + seg);
            Ws[row][seg + 0] = f2tf32(v.x);
            Ws[row][seg + 1] = f2tf32(v.y);
            Ws[row][seg + 2] = f2tf32(v.z);
            Ws[row][seg + 3] = f2tf32(v.w);
        }
        __syncthreads();

        #pragma unroll
        for (int km = 0; km < 4; km++) {
            const int k8 = km * 8;
            uint32_t a[2][4];
            #pragma unroll
            for (int m = 0; m < 2; m++) {
                const int rb = wm * 32 + m * 16;
                a[m][0] = As[rb + gID    ][k8 + tig    ];
                a[m][1] = As[rb + gID + 8][k8 + tig    ];
                a[m][2] = As[rb + gID    ][k8 + tig + 4];
                a[m][3] = As[rb + gID + 8][k8 + tig + 4];
            }
            #pragma unroll
            for (int n = 0; n < 8; n++) {
                const int cb = wn * 64 + n * 8;
                const uint32_t b0 = Ws[k8 + tig    ][cb + gID];
                const uint32_t b1 = Ws[k8 + tig + 4][cb + gID];
                mma16n8k8(c[0][n], a[0], b0, b1);
                mma16n8k8(c[1][n], a[1], b0, b1);
            }
        }
        __syncthreads();
    }

    // Epilogue: convert to fp16, write half2 pairs
    #pragma unroll
    for (int m = 0; m < 2; m++) {
        const int r0 = row0 + wm * 32 + m * 16 + gID;
        const int r1 = r0 + 8;
        #pragma unroll
        for (int n = 0; n < 8; n++) {
            const int cb = wn * 64 + n * 8 + 2 * tig;
            if (r0 < M)
                *(__half2*)(g_xw + (size_t)r0 * D + cb) =
                    __floats2half2_rn(c[m][n][0], c[m][n][1]);
            if (r1 < M)
                *(__half2*)(g_xw + (size_t)r1 * D + cb) =
                    __floats2half2_rn(c[m][n][2], c[m][n][3]);
        }
    }
}

// ---------------------------------------------------------------------------
// Kernel 2: out = A @ xw + bias. One warp per node; lane l owns dims [4l,4l+4).
// fp16 gather rows (256 B/edge), fp32 accumulate, 8-deep gather batches.
// ---------------------------------------------------------------------------
__global__ void __launch_bounds__(256) spmm_kernel(
    const int*   __restrict__ ecol,   // [E]
    const float* __restrict__ eval,   // [E]
    const float* __restrict__ bias,   // [128]
    float*       __restrict__ out,    // [N, 128]
    int N)
{
    const int warp_in_blk = threadIdx.x >> 5;
    const int lane        = threadIdx.x & 31;
    const int node        = blockIdx.x * 8 + warp_in_blk;
    if (node >= N) return;

    const int lo = g_row_ptr[node];
    const int hi = g_row_ptr[node + 1];

    float4 acc0 = make_float4(0.f, 0.f, 0.f, 0.f);
    float4 acc1 = make_float4(0.f, 0.f, 0.f, 0.f);

    for (int base = lo; base < hi; base += 32) {
        const int idx = base + lane;
        int   cc = 0;
        float vv = 0.f;
        if (idx < hi) { cc = ecol[idx]; vv = eval[idx]; }
        const int cnt = min(32, hi - base);

        if (cnt == 32) {
            #pragma unroll
            for (int jb = 0; jb < 32; jb += 8) {
                uint2 hv[8];
                float vj[8];
                #pragma unroll
                for (int u = 0; u < 8; u++) {
                    const int cj = __shfl_sync(0xffffffffu, cc, jb + u);
                    vj[u] = __shfl_sync(0xffffffffu, vv, jb + u);
                    hv[u] = *((const uint2*)(g_xw + (size_t)cj * D) + lane);
                }
                #pragma unroll
                for (int u = 0; u < 8; u += 2) {
                    {
                        const float2 f0 = __half22float2(*(const __half2*)&hv[u].x);
                        const float2 f1 = __half22float2(*(const __half2*)&hv[u].y);
                        acc0.x += vj[u] * f0.x;  acc0.y += vj[u] * f0.y;
                        acc0.z += vj[u] * f1.x;  acc0.w += vj[u] * f1.y;
                    }
                    {
                        const float2 f0 = __half22float2(*(const __half2*)&hv[u+1].x);
                        const float2 f1 = __half22float2(*(const __half2*)&hv[u+1].y);
                        acc1.x += vj[u+1] * f0.x;  acc1.y += vj[u+1] * f0.y;
                        acc1.z += vj[u+1] * f1.x;  acc1.w += vj[u+1] * f1.y;
                    }
                }
            }
        } else {
            for (int j = 0; j < cnt; j++) {
                const int   cj = __shfl_sync(0xffffffffu, cc, j);
                const float vj = __shfl_sync(0xffffffffu, vv, j);
                const uint2 hv = *((const uint2*)(g_xw + (size_t)cj * D) + lane);
                const float2 f0 = __half22float2(*(const __half2*)&hv.x);
                const float2 f1 = __half22float2(*(const __half2*)&hv.y);
                acc0.x += vj * f0.x;  acc0.y += vj * f0.y;
                acc0.z += vj * f1.x;  acc0.w += vj * f1.y;
            }
        }
    }

    const float4 b4 = *((const float4*)bias + lane);
    float4 r;
    r.x = acc0.x + acc1.x + b4.x;
    r.y = acc0.y + acc1.y + b4.y;
    r.z = acc0.z + acc1.z + b4.z;
    r.w = acc0.w + acc1.w + b4.w;
    *((float4*)(out + (size_t)node * D) + lane) = r;
}

// ---------------------------------------------------------------------------
// Launch
// ---------------------------------------------------------------------------
extern "C" void kernel_launch(void* const* d_in, const int* in_sizes, int n_in,
                              void* d_out, int out_size)
{
    const float* x    = (const float*)d_in[0];   // [N,128]
    const int*   erow = (const int*)  d_in[1];   // [E] sorted
    const int*   ecol = (const int*)  d_in[2];   // [E]
    const float* eval = (const float*)d_in[3];   // [E]
    const float* Wm   = (const float*)d_in[4];   // [128,128]
    const float* bias = (const float*)d_in[5];   // [128]
    float*       out  = (float*)d_out;

    const int N = out_size / D;
    const int E = in_sizes[1];

    // Kernel 0: CSR row_ptr (8 edges/thread)
    build_row_ptr_kernel<<<(E + 2047) / 2048, 256>>>(erow, N, E);

    // Kernel 1: xw = x @ W (tf32 tensor cores, fp16 store)
    xw_kernel<<<(N + 127) / 128, 256>>>(x, Wm, N);

    // Kernel 2: out = A @ xw + bias
    spmm_kernel<<<(N + 7) / 8, 256>>>(ecol, eval, bias, out, N);
}

// round 11
// speedup vs baseline: 2.2371x; 1.0429x over previous
#include <cuda_runtime.h>
#include <cuda_fp16.h>
#include <cuda_bf16.h>
#include <cstdint>

// ---------------------------------------------------------------------------
// GCN layer, reordered:  out = A @ (x @ W) + bias
//   Kernel A (fused): blocks [0,G1)  : xw = x @ W  (tf32 mma, cp.async 2-stage,
//                                      fp32 accum, fp16 store)
//                     blocks [G1,..) : CSR row_ptr from sorted COO rows
//   Kernel B: out = A @ xw + bias    (CSR SpMM, warp/node, fp16 gather,
//                                     fp32 accumulate, 8-deep gather batches)
// ---------------------------------------------------------------------------

#define D 128
#define MAX_NODES 100000

__device__ __half g_xw[(size_t)MAX_NODES * D];   // fp16: halves gather traffic
__device__ int    g_row_ptr[MAX_NODES + 1];

__device__ __forceinline__ uint32_t f2tf32(float f) {
    uint32_t r;
    asm("cvt.rna.tf32.f32 %0, %1;" : "=r"(r) : "f"(f));
    return r;
}

__device__ __forceinline__ void mma16n8k8(float* c, const uint32_t* a,
                                          uint32_t b0, uint32_t b1) {
    asm volatile(
        "mma.sync.aligned.m16n8k8.row.col.f32.tf32.tf32.f32 "
        "{%0,%1,%2,%3}, {%4,%5,%6,%7}, {%8,%9}, {%0,%1,%2,%3};"
        : "+f"(c[0]), "+f"(c[1]), "+f"(c[2]), "+f"(c[3])
        : "r"(a[0]), "r"(a[1]), "r"(a[2]), "r"(a[3]), "r"(b0), "r"(b1));
}

__device__ __forceinline__ void cp_async16(void* smem_dst, const void* gsrc, int src_bytes) {
    uint32_t sa = (uint32_t)__cvta_generic_to_shared(smem_dst);
    asm volatile("cp.async.cg.shared.global [%0], [%1], 16, %2;\n"
                 :: "r"(sa), "l"(gsrc), "r"(src_bytes));
}
__device__ __forceinline__ void cp_async_commit() {
    asm volatile("cp.async.commit_group;\n");
}
template <int NG>
__device__ __forceinline__ void cp_async_wait() {
    asm volatile("cp.async.wait_group %0;\n" :: "n"(NG));
}

// Dynamic smem layout (floats):
//   AS(st, r, c) : 2 x [128][36]  at offset st*4608 + r*36 + c
//   WS(st, r, c) : 2 x [32][136]  at offset 9216 + st*4352 + r*136 + c
#define AS_OFF(st, r, c) ((st) * 4608 + (r) * 36 + (c))
#define WS_OFF(st, r, c) (9216 + (st) * 4352 + (r) * 136 + (c))
#define SMEM_FLOATS (9216 + 2 * 4352)

// ---------------------------------------------------------------------------
// Fused kernel: GEMM blocks + row_ptr blocks (independent work, one launch)
// ---------------------------------------------------------------------------
__global__ void __launch_bounds__(256) fused_gemm_rowptr_kernel(
    const float* __restrict__ x,     // [M, 128]
    const float* __restrict__ Wm,    // [128, 128]
    const int*   __restrict__ erow,  // [E] sorted
    int M, int N, int E, int G1)
{
    extern __shared__ float sm[];
    const int tid = threadIdx.x;

    if (blockIdx.x >= G1) {
        // ----- row_ptr part: 16 edges per thread (4x int4) -----
        const int t    = (blockIdx.x - G1) * 256 + tid;
        const int base = t * 16;
        if (base >= E) return;

        int v[17];
        v[0] = (base == 0) ? -1 : erow[base - 1];

        const int cnt = min(16, E - base);
        if (cnt == 16) {
            #pragma unroll
            for (int q = 0; q < 4; q++) {
                const int4 a = *(const int4*)(erow + base + q * 4);
                v[q * 4 + 1] = a.x; v[q * 4 + 2] = a.y;
                v[q * 4 + 3] = a.z; v[q * 4 + 4] = a.w;
            }
        } else {
            for (int k = 0; k < cnt; k++) v[k + 1] = erow[base + k];
        }

        #pragma unroll
        for (int k = 1; k <= 16; k++) {
            if (k <= cnt) {
                for (int r = v[k - 1] + 1; r <= v[k]; r++)
                    g_row_ptr[r] = base + k - 1;
            }
        }
        if (base + cnt == E) {
            for (int r = v[cnt] + 1; r <= N; r++) g_row_ptr[r] = E;
        }
        return;
    }

    // ----- GEMM part: 128x128 tile, 2-stage cp.async pipeline -----
    const int lane = tid & 31;
    const int wid  = tid >> 5;
    const int wm   = wid & 3;
    const int wn   = wid >> 2;
    const int row0 = blockIdx.x * 128;

    const int gID = lane >> 2;
    const int tig = lane & 3;

    // Per-thread load coords (4 float4 each for As and Ws per chunk)
    int a_row[4], a_seg[4], w_row[4], w_seg[4];
    #pragma unroll
    for (int it = 0; it < 4; it++) {
        int s = tid + it * 256;
        a_row[it] = s >> 3;
        a_seg[it] = (s & 7) * 4;
        w_row[it] = s >> 5;
        w_seg[it] = (s & 31) * 4;
    }

    float c[2][8][4];
    #pragma unroll
    for (int m = 0; m < 2; m++)
        #pragma unroll
        for (int n = 0; n < 8; n++)
            #pragma unroll
            for (int i = 0; i < 4; i++) c[m][n][i] = 0.f;

    // Prefetch chunk 0 into stage 0
    #pragma unroll
    for (int it = 0; it < 4; it++) {
        const int gr = row0 + a_row[it];
        cp_async16(&sm[AS_OFF(0, a_row[it], a_seg[it])],
                   x + (size_t)gr * D + 0 + a_seg[it], gr < M ? 16 : 0);
    }
    #pragma unroll
    for (int it = 0; it < 4; it++) {
        cp_async16(&sm[WS_OFF(0, w_row[it], w_seg[it])],
                   Wm + (size_t)(0 + w_row[it]) * D + w_seg[it], 16);
    }
    cp_async_commit();

    #pragma unroll
    for (int kcc = 0; kcc < 4; kcc++) {
        const int st = kcc & 1;
        // Prefetch next chunk into the other stage
        if (kcc < 3) {
            const int kn = (kcc + 1) * 32;
            const int sn = st ^ 1;
            #pragma unroll
            for (int it = 0; it < 4; it++) {
                const int gr = row0 + a_row[it];
                cp_async16(&sm[AS_OFF(sn, a_row[it], a_seg[it])],
                           x + (size_t)gr * D + kn + a_seg[it], gr < M ? 16 : 0);
            }
            #pragma unroll
            for (int it = 0; it < 4; it++) {
                cp_async16(&sm[WS_OFF(sn, w_row[it], w_seg[it])],
                           Wm + (size_t)(kn + w_row[it]) * D + w_seg[it], 16);
            }
            cp_async_commit();
            cp_async_wait<1>();
        } else {
            cp_async_wait<0>();
        }
        __syncthreads();

        #pragma unroll
        for (int km = 0; km < 4; km++) {
            const int k8 = km * 8;
            uint32_t a[2][4];
            #pragma unroll
            for (int m = 0; m < 2; m++) {
                const int rb = wm * 32 + m * 16;
                a[m][0] = f2tf32(sm[AS_OFF(st, rb + gID,     k8 + tig    )]);
                a[m][1] = f2tf32(sm[AS_OFF(st, rb + gID + 8, k8 + tig    )]);
                a[m][2] = f2tf32(sm[AS_OFF(st, rb + gID,     k8 + tig + 4)]);
                a[m][3] = f2tf32(sm[AS_OFF(st, rb + gID + 8, k8 + tig + 4)]);
            }
            #pragma unroll
            for (int n = 0; n < 8; n++) {
                const int cb = wn * 64 + n * 8;
                const uint32_t b0 = f2tf32(sm[WS_OFF(st, k8 + tig,     cb + gID)]);
                const uint32_t b1 = f2tf32(sm[WS_OFF(st, k8 + tig + 4, cb + gID)]);
                mma16n8k8(c[0][n], a[0], b0, b1);
                mma16n8k8(c[1][n], a[1], b0, b1);
            }
        }
        __syncthreads();
    }

    // Epilogue: convert to fp16, write half2 pairs
    #pragma unroll
    for (int m = 0; m < 2; m++) {
        const int r0 = row0 + wm * 32 + m * 16 + gID;
        const int r1 = r0 + 8;
        #pragma unroll
        for (int n = 0; n < 8; n++) {
            const int cb = wn * 64 + n * 8 + 2 * tig;
            if (r0 < M)
                *(__half2*)(g_xw + (size_t)r0 * D + cb) =
                    __floats2half2_rn(c[m][n][0], c[m][n][1]);
            if (r1 < M)
                *(__half2*)(g_xw + (size_t)r1 * D + cb) =
                    __floats2half2_rn(c[m][n][2], c[m][n][3]);
        }
    }
}

// ---------------------------------------------------------------------------
// Kernel B: out = A @ xw + bias. One warp per node; lane l owns dims [4l,4l+4).
// fp16 gather rows (256 B/edge), fp32 accumulate, 8-deep gather batches.
// ---------------------------------------------------------------------------
__global__ void __launch_bounds__(256) spmm_kernel(
    const int*   __restrict__ ecol,   // [E]
    const float* __restrict__ eval,   // [E]
    const float* __restrict__ bias,   // [128]
    float*       __restrict__ out,    // [N, 128]
    int N)
{
    const int warp_in_blk = threadIdx.x >> 5;
    const int lane        = threadIdx.x & 31;
    const int node        = blockIdx.x * 8 + warp_in_blk;
    if (node >= N) return;

    const int lo = g_row_ptr[node];
    const int hi = g_row_ptr[node + 1];

    float4 acc0 = make_float4(0.f, 0.f, 0.f, 0.f);
    float4 acc1 = make_float4(0.f, 0.f, 0.f, 0.f);

    for (int base = lo; base < hi; base += 32) {
        const int idx = base + lane;
        int   cc = 0;
        float vv = 0.f;
        if (idx < hi) { cc = ecol[idx]; vv = eval[idx]; }
        const int cnt = min(32, hi - base);

        if (cnt == 32) {
            #pragma unroll
            for (int jb = 0; jb < 32; jb += 8) {
                uint2 hv[8];
                float vj[8];
                #pragma unroll
                for (int u = 0; u < 8; u++) {
                    const int cj = __shfl_sync(0xffffffffu, cc, jb + u);
                    vj[u] = __shfl_sync(0xffffffffu, vv, jb + u);
                    hv[u] = *((const uint2*)(g_xw + (size_t)cj * D) + lane);
                }
                #pragma unroll
                for (int u = 0; u < 8; u += 2) {
                    {
                        const float2 f0 = __half22float2(*(const __half2*)&hv[u].x);
                        const float2 f1 = __half22float2(*(const __half2*)&hv[u].y);
                        acc0.x += vj[u] * f0.x;  acc0.y += vj[u] * f0.y;
                        acc0.z += vj[u] * f1.x;  acc0.w += vj[u] * f1.y;
                    }
                    {
                        const float2 f0 = __half22float2(*(const __half2*)&hv[u+1].x);
                        const float2 f1 = __half22float2(*(const __half2*)&hv[u+1].y);
                        acc1.x += vj[u+1] * f0.x;  acc1.y += vj[u+1] * f0.y;
                        acc1.z += vj[u+1] * f1.x;  acc1.w += vj[u+1] * f1.y;
                    }
                }
            }
        } else {
            for (int j = 0; j < cnt; j++) {
                const int   cj = __shfl_sync(0xffffffffu, cc, j);
                const float vj = __shfl_sync(0xffffffffu, vv, j);
                const uint2 hv = *((const uint2*)(g_xw + (size_t)cj * D) + lane);
                const float2 f0 = __half22float2(*(const __half2*)&hv.x);
                const float2 f1 = __half22float2(*(const __half2*)&hv.y);
                acc0.x += vj * f0.x;  acc0.y += vj * f0.y;
                acc0.z += vj * f1.x;  acc0.w += vj * f1.y;
            }
        }
    }

    const float4 b4 = *((const float4*)bias + lane);
    float4 r;
    r.x = acc0.x + acc1.x + b4.x;
    r.y = acc0.y + acc1.y + b4.y;
    r.z = acc0.z + acc1.z + b4.z;
    r.w = acc0.w + acc1.w + b4.w;
    *((float4*)(out + (size_t)node * D) + lane) = r;
}

// ---------------------------------------------------------------------------
// Launch
// ---------------------------------------------------------------------------
extern "C" void kernel_launch(void* const* d_in, const int* in_sizes, int n_in,
                              void* d_out, int out_size)
{
    const float* x    = (const float*)d_in[0];   // [N,128]
    const int*   erow = (const int*)  d_in[1];   // [E] sorted
    const int*   ecol = (const int*)  d_in[2];   // [E]
    const float* eval = (const float*)d_in[3];   // [E]
    const float* Wm   = (const float*)d_in[4];   // [128,128]
    const float* bias = (const float*)d_in[5];   // [128]
    float*       out  = (float*)d_out;

    const int N = out_size / D;
    const int E = in_sizes[1];

    const int G1 = (N + 127) / 128;              // gemm blocks
    const int G2 = (E + 4095) / 4096;            // row_ptr blocks (16 edges/thread)
    const int smem_bytes = SMEM_FLOATS * 4;      // ~71.7 KB

    cudaFuncSetAttribute(fused_gemm_rowptr_kernel,
                         cudaFuncAttributeMaxDynamicSharedMemorySize, smem_bytes);

    // Kernel A: fused GEMM + row_ptr (independent block families, one launch)
    fused_gemm_rowptr_kernel<<<G1 + G2, 256, smem_bytes>>>(x, Wm, erow, N, N, E, G1);

    // Kernel B: out = A @ xw + bias
    spmm_kernel<<<(N + 7) / 8, 256>>>(ecol, eval, bias, out, N);
}